// round 1
// baseline (speedup 1.0000x reference)
#include <cuda_runtime.h>
#include <cuda_bf16.h>
#include <cstdint>

#define B_   128
#define S_   512
#define D_   2048
#define N_   128
#define NN_  (N_ * N_)

// ---------------- scratch (device globals; no allocation) ----------------
__device__ __align__(16) float g_mean[B_ * D_];        // 1 MB
__device__ __align__(16) float g_ctx [B_ * D_];        // 1 MB
__device__ __align__(16) float g_warp[B_ * NN_];       // 8 MB
__device__ __align__(16) float g_part[64 * B_ * N_];   // 4 MB split-K partials for raw
__device__ __align__(16) float g_raw [B_ * N_];        // 64 KB

// ---------------- helpers ----------------
__device__ __forceinline__ void cp_async16(void* smem, const void* gmem) {
    uint32_t s = (uint32_t)__cvta_generic_to_shared(smem);
    asm volatile("cp.async.cg.shared.global [%0], [%1], 16;\n" :: "r"(s), "l"(gmem));
}
__device__ __forceinline__ uint32_t f2bf2(float lo, float hi) {
    uint32_t r;
    asm("cvt.rn.bf16x2.f32 %0, %1, %2;" : "=r"(r) : "f"(hi), "f"(lo));  // first src -> upper half
    return r;
}
__device__ __forceinline__ void mma_bf16(float* c,
                                         uint32_t a0, uint32_t a1, uint32_t a2, uint32_t a3,
                                         uint32_t b0, uint32_t b1) {
    asm volatile(
        "mma.sync.aligned.m16n8k16.row.col.f32.bf16.bf16.f32 "
        "{%0,%1,%2,%3}, {%4,%5,%6,%7}, {%8,%9}, {%0,%1,%2,%3};"
        : "+f"(c[0]), "+f"(c[1]), "+f"(c[2]), "+f"(c[3])
        : "r"(a0), "r"(a1), "r"(a2), "r"(a3), "r"(b0), "r"(b1));
}

// ---------------- kernel 1: mean over sequence ----------------
// grid 512 (= B * 4 chunks), block 128 threads; each thread reduces one float4 column.
__global__ void k_mean(const float4* __restrict__ x4, float4* __restrict__ mean4) {
    int b  = blockIdx.x >> 2;
    int d4 = ((blockIdx.x & 3) << 7) + threadIdx.x;            // 0..511  (D/4 = 512)
    const float4* p = x4 + (size_t)b * (S_ * D_ / 4) + d4;
    float4 a0 = make_float4(0.f,0.f,0.f,0.f), a1 = a0, a2 = a0, a3 = a0;
    #pragma unroll 2
    for (int s = 0; s < S_; s += 4) {
        float4 v0 = p[(s+0) * (D_/4)];
        float4 v1 = p[(s+1) * (D_/4)];
        float4 v2 = p[(s+2) * (D_/4)];
        float4 v3 = p[(s+3) * (D_/4)];
        a0.x += v0.x; a0.y += v0.y; a0.z += v0.z; a0.w += v0.w;
        a1.x += v1.x; a1.y += v1.y; a1.z += v1.z; a1.w += v1.w;
        a2.x += v2.x; a2.y += v2.y; a2.z += v2.z; a2.w += v2.w;
        a3.x += v3.x; a3.y += v3.y; a3.z += v3.z; a3.w += v3.w;
    }
    float4 m;
    const float inv = 1.f / (float)S_;
    m.x = (a0.x + a1.x + a2.x + a3.x) * inv;
    m.y = (a0.y + a1.y + a2.y + a3.y) * inv;
    m.z = (a0.z + a1.z + a2.z + a3.z) * inv;
    m.w = (a0.w + a1.w + a2.w + a3.w) * inv;
    mean4[b * (D_/4) + d4] = m;
}

// ---------------- kernel 2/4: bf16 MMA GEMM, out[M=128, Nfull] = A[128,2048] @ Bm[Nfull,2048]^T ----
// EPI: 0 = plain, 1 = +bias, 2 = (+bias)*0.1
// Block: full M=128 x NT columns. 256 threads = 8 warps; warp w owns rows [16w,16w+16).
// fp32 tiles in smem via cp.async (2-stage), converted to bf16x2 at fragment load.
#define KT 32
#define PAD 36  /* fp32 row stride in smem: 144 B, 16B-aligned, reduces LDS conflicts */

template<int NT, int EPI>
__global__ void k_gemm(const float* __restrict__ A, const float* __restrict__ Bm,
                       const float* __restrict__ bias, float* __restrict__ out, int Nfull) {
    extern __shared__ float sm[];
    float (*As)[PAD] = reinterpret_cast<float(*)[PAD]>(sm);               // [2*128][PAD]
    float (*Bs)[PAD] = reinterpret_cast<float(*)[PAD]>(sm + 2 * 128 * PAD); // [2*NT][PAD]

    const int tid  = threadIdx.x;
    const int warp = tid >> 5, lane = tid & 31;
    const int n0   = blockIdx.x * NT;
    const int r    = lane >> 2, c = lane & 3;
    const int wm   = warp * 16;

    float acc[NT/8][4];
    #pragma unroll
    for (int j = 0; j < NT/8; j++)
        acc[j][0] = acc[j][1] = acc[j][2] = acc[j][3] = 0.f;

    auto load_tiles = [&](int st, int k0) {
        #pragma unroll
        for (int u = 0; u < 4; u++) {                 // A tile: 128x32 fp32 = 1024 float4
            int i  = tid + u * 256;
            int rr = i >> 3, cc = (i & 7) * 4;
            cp_async16(&As[st * 128 + rr][cc], &A[rr * D_ + k0 + cc]);
        }
        #pragma unroll
        for (int u = 0; u < NT/32; u++) {             // B tile: NTx32 fp32
            int i  = tid + u * 256;
            int rr = i >> 3, cc = (i & 7) * 4;
            cp_async16(&Bs[st * NT + rr][cc], &Bm[(size_t)(n0 + rr) * D_ + k0 + cc]);
        }
        asm volatile("cp.async.commit_group;\n");
    };

    load_tiles(0, 0);
    const int NK = D_ / KT;   // 64
    for (int kt = 0; kt < NK; kt++) {
        int st = kt & 1;
        if (kt + 1 < NK) {
            load_tiles(st ^ 1, (kt + 1) * KT);
            asm volatile("cp.async.wait_group 1;\n");
        } else {
            asm volatile("cp.async.wait_group 0;\n");
        }
        __syncthreads();

        #pragma unroll
        for (int h = 0; h < 2; h++) {
            int kb = h * 16 + 2 * c;
            float2 v;
            uint32_t a0, a1, a2, a3;
            v = *(const float2*)&As[st*128 + wm + r    ][kb    ]; a0 = f2bf2(v.x, v.y);
            v = *(const float2*)&As[st*128 + wm + r + 8][kb    ]; a1 = f2bf2(v.x, v.y);
            v = *(const float2*)&As[st*128 + wm + r    ][kb + 8]; a2 = f2bf2(v.x, v.y);
            v = *(const float2*)&As[st*128 + wm + r + 8][kb + 8]; a3 = f2bf2(v.x, v.y);
            #pragma unroll
            for (int j = 0; j < NT/8; j++) {
                uint32_t b0, b1;
                v = *(const float2*)&Bs[st*NT + j*8 + r][kb    ]; b0 = f2bf2(v.x, v.y);
                v = *(const float2*)&Bs[st*NT + j*8 + r][kb + 8]; b1 = f2bf2(v.x, v.y);
                mma_bf16(acc[j], a0, a1, a2, a3, b0, b1);
            }
        }
        __syncthreads();
    }

    #pragma unroll
    for (int j = 0; j < NT/8; j++) {
        int col = n0 + j * 8 + 2 * c;
        int row = wm + r;
        float bv0 = 0.f, bv1 = 0.f;
        if (EPI >= 1) { bv0 = bias[col]; bv1 = bias[col + 1]; }
        float o00 = acc[j][0] + bv0, o01 = acc[j][1] + bv1;
        float o10 = acc[j][2] + bv0, o11 = acc[j][3] + bv1;
        if (EPI == 2) { o00 *= 0.1f; o01 *= 0.1f; o10 *= 0.1f; o11 *= 0.1f; }
        out[(size_t)row       * Nfull + col    ] = o00;
        out[(size_t)row       * Nfull + col + 1] = o01;
        out[(size_t)(row + 8) * Nfull + col    ] = o10;
        out[(size_t)(row + 8) * Nfull + col + 1] = o11;
    }
}

// ---------------- kernel 3a: raw-score split-K partials (fp32, deterministic) ----------------
// grid 64 (K chunks of 32), block 256. part[ks][b][j] = sum_{k in chunk} ctx[b][k]*rs[j][k]
__global__ void k_rawpart(const float* __restrict__ ctx, const float* __restrict__ rs,
                          float* __restrict__ part) {
    __shared__ float cs [128][PAD];
    __shared__ float rss[128][PAD];
    const int tid = threadIdx.x;
    const int k0  = blockIdx.x * 32;
    #pragma unroll
    for (int u = 0; u < 4; u++) {
        int i  = tid + u * 256;
        int rr = i >> 3, cc = (i & 7) * 4;
        *(float4*)&cs [rr][cc] = *(const float4*)&ctx[rr * D_ + k0 + cc];
        *(float4*)&rss[rr][cc] = *(const float4*)&rs [rr * D_ + k0 + cc];
    }
    __syncthreads();
    const int bb = tid >> 4;   // 0..15
    const int jj = tid & 15;   // 0..15
    float a[8][8];
    #pragma unroll
    for (int u = 0; u < 8; u++)
        #pragma unroll
        for (int v = 0; v < 8; v++) a[u][v] = 0.f;
    for (int k = 0; k < 32; k++) {
        float cv[8], rv[8];
        #pragma unroll
        for (int u = 0; u < 8; u++) { cv[u] = cs[bb + 16*u][k]; rv[u] = rss[jj + 16*u][k]; }
        #pragma unroll
        for (int u = 0; u < 8; u++)
            #pragma unroll
            for (int v = 0; v < 8; v++) a[u][v] += cv[u] * rv[v];
    }
    float* po = part + (size_t)blockIdx.x * NN_;
    #pragma unroll
    for (int u = 0; u < 8; u++)
        #pragma unroll
        for (int v = 0; v < 8; v++)
            po[(bb + 16*u) * N_ + (jj + 16*v)] = a[u][v];
}

// ---------------- kernel 3b: reduce partials ----------------
__global__ void k_rawred(const float* __restrict__ part, float* __restrict__ raw) {
    int i = blockIdx.x * blockDim.x + threadIdx.x;   // 0..16383
    float s = 0.f;
    #pragma unroll 8
    for (int ks = 0; ks < 64; ks++) s += part[(size_t)ks * NN_ + i];
    raw[i] = s;
}

// ---------------- kernel 5: softmax + warped scores + sigmoid ----------------
// grid 128 (b), block 128 (thread = row i). smem holds logits [128][129] + raw row.
__global__ void k_final(const float* __restrict__ adj, const float* __restrict__ warp_,
                        const float* __restrict__ raw, float* __restrict__ out) {
    extern __shared__ float sm[];
    float (*s)[129] = reinterpret_cast<float(*)[129]>(sm);
    float* raws = sm + 128 * 129;
    const int b = blockIdx.x, t = threadIdx.x;
    raws[t] = raw[b * N_ + t];
    const float* wp = warp_ + (size_t)b * NN_;
    for (int idx = t; idx < NN_; idx += 128)
        s[idx >> 7][idx & 127] = adj[idx] + wp[idx];
    __syncthreads();
    float m = -1e30f;
    #pragma unroll 4
    for (int j = 0; j < N_; j++) m = fmaxf(m, s[t][j]);
    float sum = 0.f, dot = 0.f;
    #pragma unroll 4
    for (int j = 0; j < N_; j++) {
        float e = __expf(s[t][j] - m);
        sum += e;
        dot += e * raws[j];
    }
    float w = dot / sum;
    out[b * N_ + t] = 1.f / (1.f + __expf(-w));
}

// ---------------- launch ----------------
extern "C" void kernel_launch(void* const* d_in, const int* in_sizes, int n_in,
                              void* d_out, int out_size) {
    const float* x   = (const float*)d_in[0];   // [128,512,2048]
    const float* rs  = (const float*)d_in[1];   // [128,2048]
    const float* Wc  = (const float*)d_in[2];   // [2048,2048]
    const float* bc  = (const float*)d_in[3];   // [2048]
    const float* Ww  = (const float*)d_in[4];   // [16384,2048]
    const float* bw  = (const float*)d_in[5];   // [16384]
    const float* adj = (const float*)d_in[6];   // [128,128]
    float* out = (float*)d_out;

    float *p_mean, *p_ctx, *p_warp, *p_part, *p_raw;
    cudaGetSymbolAddress((void**)&p_mean, g_mean);
    cudaGetSymbolAddress((void**)&p_ctx,  g_ctx);
    cudaGetSymbolAddress((void**)&p_warp, g_warp);
    cudaGetSymbolAddress((void**)&p_part, g_part);
    cudaGetSymbolAddress((void**)&p_raw,  g_raw);

    // 1. mean over S  (HBM-bound, ~512 MB)
    k_mean<<<B_ * 4, 128>>>((const float4*)x, (float4*)p_mean);

    // 2. context = mean @ Wc^T + bc   (bf16 MMA, NT=32 -> 64 blocks)
    {
        size_t sh = (size_t)(2 * 128 * PAD + 2 * 32 * PAD) * sizeof(float);
        cudaFuncSetAttribute(k_gemm<32, 1>, cudaFuncAttributeMaxDynamicSharedMemorySize, (int)sh);
        k_gemm<32, 1><<<D_ / 32, 256, sh>>>(p_mean, Wc, bc, p_ctx, D_);
    }

    // 3. raw = ctx @ rs^T (fp32 split-K, deterministic)
    k_rawpart<<<64, 256>>>(p_ctx, rs, p_part);
    k_rawred<<<64, 256>>>(p_part, p_raw);

    // 4. warp = 0.1*(ctx @ Ww^T + bw)  (bf16 MMA, NT=128 -> 128 blocks, HBM-streaming)
    {
        size_t sh = (size_t)(2 * 128 * PAD + 2 * 128 * PAD) * sizeof(float);
        cudaFuncSetAttribute(k_gemm<128, 2>, cudaFuncAttributeMaxDynamicSharedMemorySize, (int)sh);
        k_gemm<128, 2><<<NN_ / 128, 256, sh>>>(p_ctx, Ww, bw, p_warp, NN_);
    }

    // 5. softmax(adj + warp) @ raw -> sigmoid
    {
        size_t sh = (size_t)(128 * 129 + 128) * sizeof(float);
        cudaFuncSetAttribute(k_final, cudaFuncAttributeMaxDynamicSharedMemorySize, (int)sh);
        k_final<<<B_, 128, sh>>>(adj, p_warp, p_raw, out);
    }
}